// round 11
// baseline (speedup 1.0000x reference)
#include <cuda_runtime.h>
#include <cuda_bf16.h>

// VisbilityMask: out[b, ch, r, c] = 1 - (tn_z(vertex r,c) >= 0)
//
// Reference reduces (scatter .set last-wins + nonnegative angle weights =>
// only the SIGN of one face normal's z matters per vertex):
//   r>=1, c>=1 : face f2 of cell (r-1,c-1): p1=(r,c-1) p0=(r-1,c) p2=(r,c)
//   r==0, c>=1 : face f1 of cell (0,c-1):   p1=(1,c-1) p0=(0,c-1) p2=(0,c)
//   c==0       : same face as c==1  =>  mask[r][0] == mask[r][1]  (all r)
// e0 = P(p1)-P(p0), e2 = P(p1)-P(p2), tn_z = e0x*e2y - e0y*e2x (x,y only).
//
// 2-row tile per thread: rows (2i, 2i+1) computed from rows 2i-1, 2i, 2i+1.
// 6x LDG.128 + 6x STG.128 per 8 vertices (was 14 mem-instr / 8), read
// traffic 8.4MB -> 6.3MB. c-1 neighbors via __shfl_up (rm row needs none);
// real neighbor loads only on lane 0.

#define G     512
#define NV    (G * G)          // 262144
#define BATCH 4
#define FULL  0xFFFFFFFFu

// sign of cross((p1-p0),(p1-p2)).z with explicit rn mul/sub (no FMA
// contraction => bit-identical sign to XLA's mul,mul,sub sequence)
__device__ __forceinline__ float vis(float p1x, float p1y,
                                     float p0x, float p0y,
                                     float p2x, float p2y)
{
    const float e0x = p1x - p0x;
    const float e0y = p1y - p0y;
    const float e2x = p1x - p2x;
    const float e2y = p1y - p2y;
    const float tnz = __fsub_rn(__fmul_rn(e0x, e2y), __fmul_rn(e0y, e2x));
    return (tnz >= 0.0f) ? 0.0f : 1.0f;
}

__global__ __launch_bounds__(256, 5)
void visibility_mask_v6(const float* __restrict__ X, float* __restrict__ out)
{
    const int tid = blockIdx.x * blockDim.x + threadIdx.x;  // 0 .. BATCH*32768-1
    const int b  = tid >> 15;            // 256 row-pairs * 128 quads = 32768
    const int q  = tid & 32767;
    const int i  = q >> 7;               // row-pair index 0..255
    const int cq = q & 127;              // quad index; c0 = 4*cq
    const int lane = threadIdx.x & 31;

    const int r0 = 2 * i;
    const int r1 = 2 * i + 1;
    const int rm = (i > 0) ? (2 * i - 1) : 1;   // row above r0 (or row 1 at i==0)

    const float* xs = X + (size_t)b * 3 * NV;   // x-plane
    const float* ys = xs + NV;                   // y-plane

    const float* A0x = xs + (size_t)r0 * G;
    const float* A0y = ys + (size_t)r0 * G;
    const float* A1x = xs + (size_t)r1 * G;
    const float* A1y = ys + (size_t)r1 * G;

    // 6 vector loads per thread (8 vertices).
    const float4 a0x = ((const float4*)A0x)[cq];
    const float4 a0y = ((const float4*)A0y)[cq];
    const float4 a1x = ((const float4*)A1x)[cq];
    const float4 a1y = ((const float4*)A1y)[cq];
    const float4 mx  = ((const float4*)(xs + (size_t)rm * G))[cq];
    const float4 my  = ((const float4*)(ys + (size_t)rm * G))[cq];

    // c0-1 neighbors for rows r0, r1 (rm row never needs c-1).
    float a0m1x = __shfl_up_sync(FULL, a0x.w, 1);
    float a0m1y = __shfl_up_sync(FULL, a0y.w, 1);
    float a1m1x = __shfl_up_sync(FULL, a1x.w, 1);
    float a1m1y = __shfl_up_sync(FULL, a1y.w, 1);
    if (lane == 0 && cq > 0) {           // warp boundary inside a row
        const int cm1 = 4 * cq - 1;
        a0m1x = __ldg(A0x + cm1);
        a0m1y = __ldg(A0y + cm1);
        a1m1x = __ldg(A1x + cm1);
        a1m1y = __ldg(A1y + cm1);
    }
    // (cq==0: neighbor values unused — o*0 overwritten by o*1 below.)

    // Row r0
    float p00, p01, p02, p03;
    if (i > 0) {   // warp-uniform
        // p1 = A0[c-1], p0 = M[c], p2 = A0[c]
        p00 = vis(a0m1x, a0m1y, mx.x, my.x, a0x.x, a0y.x);
        p01 = vis(a0x.x, a0y.x, mx.y, my.y, a0x.y, a0y.y);
        p02 = vis(a0x.y, a0y.y, mx.z, my.z, a0x.z, a0y.z);
        p03 = vis(a0x.z, a0y.z, mx.w, my.w, a0x.w, a0y.w);
    } else {
        // r0 == 0: p1 = row1[c-1] = A1[c-1], p0 = A0[c-1], p2 = A0[c]
        p00 = vis(a1m1x, a1m1y, a0m1x, a0m1y, a0x.x, a0y.x);
        p01 = vis(a1x.x, a1y.x, a0x.x, a0y.x, a0x.y, a0y.y);
        p02 = vis(a1x.y, a1y.y, a0x.y, a0y.y, a0x.z, a0y.z);
        p03 = vis(a1x.z, a1y.z, a0x.z, a0y.z, a0x.w, a0y.w);
    }

    // Row r1 (always >= 1): p1 = A1[c-1], p0 = A0[c], p2 = A1[c]
    float p10 = vis(a1m1x, a1m1y, a0x.x, a0y.x, a1x.x, a1y.x);
    float p11 = vis(a1x.x, a1y.x, a0x.y, a0y.y, a1x.y, a1y.y);
    float p12 = vis(a1x.y, a1y.y, a0x.z, a0y.z, a1x.z, a1y.z);
    float p13 = vis(a1x.z, a1y.z, a0x.w, a0y.w, a1x.w, a1y.w);

    if (cq == 0) { p00 = p01; p10 = p11; }   // mask[r][0] == mask[r][1]

    const float4 o0 = make_float4(p00, p01, p02, p03);
    const float4 o1 = make_float4(p10, p11, p12, p13);

    float* ob0 = out + (size_t)b * 3 * NV + (size_t)r0 * G;
    float* ob1 = ob0 + G;                     // row r1
    ((float4*)(ob0))[cq]          = o0;
    ((float4*)(ob1))[cq]          = o1;
    ((float4*)(ob0 + NV))[cq]     = o0;
    ((float4*)(ob1 + NV))[cq]     = o1;
    ((float4*)(ob0 + 2 * NV))[cq] = o0;
    ((float4*)(ob1 + 2 * NV))[cq] = o1;
}

extern "C" void kernel_launch(void* const* d_in, const int* in_sizes, int n_in,
                              void* d_out, int out_size)
{
    const float* X = (const float*)d_in[0];   // [BATCH, 3, NV] float32
    float* out = (float*)d_out;               // [BATCH, 3, G, G] float32

    const int total = BATCH * NV / 8;         // 131072 threads
    visibility_mask_v6<<<total / 256, 256>>>(X, out);
}